// round 13
// baseline (speedup 1.0000x reference)
#include <cuda_runtime.h>
#include <cuda_fp16.h>
#include <math.h>
#include <cstdint>

#define B_  8
#define T_  2048
#define E_  1024
#define H_  128
#define BT_ (B_*T_)

// scratch (allocation-free: __device__ globals)
__device__ float g_q[BT_*H_];
__device__ float g_k[BT_*H_];
__device__ float g_v[BT_*H_];
__device__ __half g_w1[3*H_*E_], g_w2[3*H_*E_];   // W^T split: [3][128 n][1024 k]

// ---------------------------------------------------------------------------
__device__ __forceinline__ uint32_t smem_u32(const void* p) {
    uint32_t a;
    asm("{ .reg .u64 t; cvta.to.shared.u64 t, %1; cvt.u32.u64 %0, t; }"
        : "=r"(a) : "l"(p));
    return a;
}

__device__ __forceinline__ void split2(float x, float y, uint32_t& hi, uint32_t& lo) {
    __half2 h = __floats2half2_rn(x, y);
    float2 f = __half22float2(h);
    __half2 l = __floats2half2_rn(x - f.x, y - f.y);
    hi = *(uint32_t*)&h; lo = *(uint32_t*)&l;
}

__device__ __forceinline__ void mma16(float* d, const uint32_t* a, const uint32_t* b) {
    asm volatile(
        "mma.sync.aligned.m16n8k16.row.col.f32.f16.f16.f32 "
        "{%0,%1,%2,%3}, {%4,%5,%6,%7}, {%8,%9}, {%0,%1,%2,%3};"
        : "+f"(d[0]), "+f"(d[1]), "+f"(d[2]), "+f"(d[3])
        : "r"(a[0]), "r"(a[1]), "r"(a[2]), "r"(a[3]), "r"(b[0]), "r"(b[1]));
}

__device__ __forceinline__ void ldsm4(uint32_t* r, uint32_t addr) {
    asm volatile("ldmatrix.sync.aligned.m8n8.x4.shared.b16 {%0,%1,%2,%3}, [%4];"
        : "=r"(r[0]), "=r"(r[1]), "=r"(r[2]), "=r"(r[3]) : "r"(addr));
}
__device__ __forceinline__ void ldsm4t(uint32_t* r, uint32_t addr) {
    asm volatile("ldmatrix.sync.aligned.m8n8.x4.trans.shared.b16 {%0,%1,%2,%3}, [%4];"
        : "=r"(r[0]), "=r"(r[1]), "=r"(r[2]), "=r"(r[3]) : "r"(addr));
}

// ---------------------------------------------------------------------------
// W -> W^T, split to fp16 halves.  grid (E/32, H/32, 3), 256 thr
// ---------------------------------------------------------------------------
__global__ void prep_w(const float* __restrict__ Wq,
                       const float* __restrict__ Wk,
                       const float* __restrict__ Wv)
{
    __shared__ float tile[32][33];
    const int sel = blockIdx.z;
    const float* __restrict__ W = (sel == 0) ? Wq : (sel == 1) ? Wk : Wv;
    const int k0 = blockIdx.x * 32, n0 = blockIdx.y * 32;
    const int tx = threadIdx.x & 31, ty = threadIdx.x >> 5;
#pragma unroll
    for (int i = 0; i < 4; i++)
        tile[ty + 8*i][tx] = W[(size_t)(k0 + ty + 8*i) * H_ + n0 + tx];
    __syncthreads();
    uint32_t* w1 = (uint32_t*)g_w1;
    uint32_t* w2 = (uint32_t*)g_w2;
#pragma unroll
    for (int r = 0; r < 2; r++) {
        int slot = r * 256 + threadIdx.x;
        int ni = slot >> 4, kp = slot & 15;
        float a = tile[2*kp][ni], b = tile[2*kp + 1][ni];
        uint32_t h, l;
        split2(a, b, h, l);
        size_t o = ((size_t)(sel * H_ + n0 + ni) * E_ + k0 + 2*kp) >> 1;
        w1[o] = h; w2[o] = l;
    }
}

// ---------------------------------------------------------------------------
// Projection: out = x @ W  via mma.sync fp16 split (3 products; 2 for V).
// CTA 64x128, 8 warps (2m x 4n), warp tile 32x32. K chunks of 32.
// ldmatrix fragments; double-buffered smem (1 sync per chunk); LDG prefetch.
// ---------------------------------------------------------------------------
#define PJS 40                       // halves per smem row
#define PJ_BUFH 15360                // halves per buffer
#define PJ_A1 0
#define PJ_A2 2560
#define PJ_B1 5120
#define PJ_B2 10240
#define PJ_SMEM (2 * PJ_BUFH * 2)    // 61440 B

__global__ __launch_bounds__(256, 2) void proj_tc(const float* __restrict__ x)
{
    extern __shared__ __half sh[];
    const uint32_t sb = smem_u32(sh);
    const int t    = threadIdx.x;
    const int wid  = t >> 5, lane = t & 31;
    const int wm   = wid >> 2, wn = wid & 3;
    const int g    = lane >> 2, tg = lane & 3;
    const int sel  = blockIdx.y;
    const int m0   = blockIdx.x * 64;

    const uint4* __restrict__ ws1 = (const uint4*)(g_w1 + (size_t)sel * H_ * E_);
    const uint4* __restrict__ ws2 = (const uint4*)(g_w2 + (size_t)sel * H_ * E_);
    float* outp = (sel == 0) ? g_q : (sel == 1) ? g_k : g_v;

    // ldmatrix lane offsets (halves)
    const int aoff = (lane & 15) * PJS + 8 * (lane >> 4);
    const int boff = ((lane & 7) + 8 * (lane >> 4)) * PJS + 8 * ((lane >> 3) & 1);

    float acc[2][4][4];
#pragma unroll
    for (int mi = 0; mi < 2; mi++)
#pragma unroll
        for (int ni = 0; ni < 4; ni++)
#pragma unroll
            for (int r = 0; r < 4; r++) acc[mi][ni][r] = 0.f;

    const int ac4 = t & 7;          // A: float4 col 0..7 in the 32-k chunk
    const int bc8 = t & 3;          // B: uint4 (8 halves) col 0..3
    float4 fa[2];
    uint4  pw1[2], pw2[2];

    auto fetch = [&](int c) {
        const int k0 = c * 32;
#pragma unroll
        for (int p = 0; p < 2; p++) {
            int row = (p * 256 + t) >> 3;
            fa[p] = *(const float4*)&x[(size_t)(m0 + row) * E_ + k0 + ac4 * 4];
        }
#pragma unroll
        for (int p = 0; p < 2; p++) {
            int row = (p * 256 + t) >> 2;
            size_t off = ((size_t)row * E_ + k0) / 8 + bc8;
            pw1[p] = ws1[off];
            pw2[p] = ws2[off];
        }
    };
    auto store = [&](int buf) {
        __half* dst = sh + buf * PJ_BUFH;
#pragma unroll
        for (int p = 0; p < 2; p++) {
            int row = (p * 256 + t) >> 3;
            float4 v = fa[p];
            uint32_t h0, l0, h1, l1;
            split2(v.x, v.y, h0, l0);
            split2(v.z, v.w, h1, l1);
            int o = row * PJS + ac4 * 4;
            *(uint32_t*)&dst[PJ_A1 + o]     = h0;
            *(uint32_t*)&dst[PJ_A1 + o + 2] = h1;
            *(uint32_t*)&dst[PJ_A2 + o]     = l0;
            *(uint32_t*)&dst[PJ_A2 + o + 2] = l1;
        }
#pragma unroll
        for (int p = 0; p < 2; p++) {
            int row = (p * 256 + t) >> 2;
            int o = row * PJS + bc8 * 8;
            *(uint4*)&dst[PJ_B1 + o] = pw1[p];
            *(uint4*)&dst[PJ_B2 + o] = pw2[p];
        }
    };

    fetch(0);
    store(0);
    __syncthreads();

    for (int c = 0; c < 32; c++) {
        const int p = c & 1;
        if (c < 31) fetch(c + 1);

        const uint32_t bufb = sb + 2 * (p * PJ_BUFH);
        const uint32_t a1b = bufb + 2 * (PJ_A1 + wm * 32 * PJS + aoff);
        const uint32_t a2b = bufb + 2 * (PJ_A2 + wm * 32 * PJS + aoff);
        const uint32_t b1b = bufb + 2 * (PJ_B1 + wn * 32 * PJS + boff);
        const uint32_t b2b = bufb + 2 * (PJ_B2 + wn * 32 * PJS + boff);

#pragma unroll
        for (int s = 0; s < 2; s++) {
            uint32_t a1[2][4], a2[2][4];
#pragma unroll
            for (int mi = 0; mi < 2; mi++) {
                ldsm4(a1[mi], a1b + 2 * (mi * 16 * PJS + s * 16));
                ldsm4(a2[mi], a2b + 2 * (mi * 16 * PJS + s * 16));
            }
#pragma unroll
            for (int ng = 0; ng < 2; ng++) {
                uint32_t b1[4], b2[4];
                ldsm4(b1, b1b + 2 * (ng * 16 * PJS + s * 16));
                ldsm4(b2, b2b + 2 * (ng * 16 * PJS + s * 16));
#pragma unroll
                for (int mi = 0; mi < 2; mi++) {
                    mma16(acc[mi][2*ng],     a1[mi], b1);
                    mma16(acc[mi][2*ng + 1], a1[mi], b1 + 2);
                    mma16(acc[mi][2*ng],     a1[mi], b2);
                    mma16(acc[mi][2*ng + 1], a1[mi], b2 + 2);
                    if (sel < 2) {
                        mma16(acc[mi][2*ng],     a2[mi], b1);
                        mma16(acc[mi][2*ng + 1], a2[mi], b1 + 2);
                    }
                }
            }
        }
        if (c < 31) {
            store(p ^ 1);
            __syncthreads();
        }
    }

#pragma unroll
    for (int mi = 0; mi < 2; mi++) {
        int row = m0 + wm * 32 + mi * 16 + g;
#pragma unroll
        for (int ni = 0; ni < 4; ni++) {
            int col = wn * 32 + ni * 8 + tg * 2;
            *(float2*)&outp[(size_t)row * H_ + col] =
                make_float2(acc[mi][ni][0], acc[mi][ni][1]);
            *(float2*)&outp[(size_t)(row + 8) * H_ + col] =
                make_float2(acc[mi][ni][2], acc[mi][ni][3]);
        }
    }
}

// ---------------------------------------------------------------------------
// Flash attention. BQ=64, BK=64. 8 warps (4m x 2n). Occupancy 2.
// QK^T: fp16 split-2, 3 products. PV: fp16 single. ldmatrix fragments.
// Single K/V buffer (2 syncs/tile); K reg-prefetch; V direct LDG->STS.
// ---------------------------------------------------------------------------
#define QH1_ 0
#define QH2_ 8704
#define KH1_ 17408
#define KH2_ 26112
#define VS_  34816
#define PH_  43520          // 64 x 72
#define HEND_ 48128
#define A_SMEM (HEND_*2 + 256*4)   // 97280 B

__global__ __launch_bounds__(256, 2) void attn_tc(float* __restrict__ out)
{
    extern __shared__ __half shh[];
    float* smax = (float*)(shh + HEND_);
    float* ssum = smax + 128;
    const uint32_t sb = smem_u32(shh);

    const int t   = threadIdx.x;
    const int wid = t >> 5, lane = t & 31;
    const int wm  = wid >> 1, wn = wid & 1;
    const int g   = lane >> 2, tg = lane & 3;
    const int qt  = (int)gridDim.x - 1 - (int)blockIdx.x;
    const int b   = blockIdx.y;
    const size_t base = (size_t)b * (T_ * H_);
    const float scale = 45.25483399593904f;   // sqrt(2048)

    // lane-pattern ldmatrix offsets (half indices)
    const int aoffQ = (lane & 15) * 136 + 8 * (lane >> 4);
    const int aoffP = (lane & 15) * 72  + 8 * (lane >> 4);
    const int boffK = ((lane & 7) + 8 * (lane >> 4)) * 136 + 8 * ((lane >> 3) & 1);
    const int voffV = ((lane & 7) + 8 * ((lane >> 3) & 1)) * 136 + 8 * (lane >> 4);

    // Q: 64x128, scaled + fp16 split
#pragma unroll
    for (int p = 0; p < 8; p++) {
        int idx = p * 256 + t;
        int row = idx >> 5, c4 = idx & 31;
        float4 v = *(const float4*)&g_q[base + (size_t)(qt * 64 + row) * H_ + c4 * 4];
        v.x *= scale; v.y *= scale; v.z *= scale; v.w *= scale;
        uint32_t h0, l0, h1, l1;
        split2(v.x, v.y, h0, l0);
        split2(v.z, v.w, h1, l1);
        int o = row * 136 + c4 * 4;
        *(uint32_t*)&shh[QH1_ + o]     = h0;
        *(uint32_t*)&shh[QH1_ + o + 2] = h1;
        *(uint32_t*)&shh[QH2_ + o]     = l0;
        *(uint32_t*)&shh[QH2_ + o + 2] = l1;
    }

    float of[8][4];
#pragma unroll
    for (int ni = 0; ni < 8; ni++)
#pragma unroll
        for (int r = 0; r < 4; r++) of[ni][r] = 0.f;
    float mrun0 = -INFINITY, mrun1 = -INFINITY;
    float lrun0 = 0.f, lrun1 = 0.f;

    const int r0 = wm * 16 + g;
    const int r1 = r0 + 8;
    const int ntiles = qt + 1;
    const int lrow = t >> 5, lc4 = t & 31;   // K/V loader mapping

    float4 pk[8];
    auto fetchK = [&](int kt) {
#pragma unroll
        for (int pp = 0; pp < 8; pp++) {
            int row = pp * 8 + lrow;
            pk[pp] = *(const float4*)&g_k[base + (size_t)(kt * 64 + row) * H_ + lc4 * 4];
        }
    };
    auto storeKV = [&](int kt) {
#pragma unroll
        for (int pp = 0; pp < 8; pp++) {
            int row = pp * 8 + lrow;
            int o = row * 136 + lc4 * 4;
            float4 v = pk[pp];
            uint32_t h0, l0, h1, l1;
            split2(v.x, v.y, h0, l0);
            split2(v.z, v.w, h1, l1);
            *(uint32_t*)&shh[KH1_ + o]     = h0;
            *(uint32_t*)&shh[KH1_ + o + 2] = h1;
            *(uint32_t*)&shh[KH2_ + o]     = l0;
            *(uint32_t*)&shh[KH2_ + o + 2] = l1;
            float4 w = *(const float4*)&g_v[base + (size_t)(kt * 64 + row) * H_ + lc4 * 4];
            __half2 va = __floats2half2_rn(w.x, w.y);
            __half2 vb = __floats2half2_rn(w.z, w.w);
            uint2 u = make_uint2(*(uint32_t*)&va, *(uint32_t*)&vb);
            *(uint2*)&shh[VS_ + o] = u;
        }
    };

    fetchK(0);

    for (int kt = 0; kt < ntiles; kt++) {
        __syncthreads();   // prev PV done reading Vs/Ps
        storeKV(kt);
        __syncthreads();
        if (kt + 1 < ntiles) fetchK(kt + 1);

        // S = Q K^T  (64x64), fp16 split-2, 3 products, ldmatrix frags
        float sf[4][4];
#pragma unroll
        for (int ni = 0; ni < 4; ni++)
#pragma unroll
            for (int r = 0; r < 4; r++) sf[ni][r] = 0.f;

        const uint32_t qb1 = sb + 2 * (QH1_ + wm * 16 * 136 + aoffQ);
        const uint32_t qb2 = sb + 2 * (QH2_ + wm * 16 * 136 + aoffQ);
        const uint32_t kb1b = sb + 2 * (KH1_ + wn * 32 * 136 + boffK);
        const uint32_t kb2b = sb + 2 * (KH2_ + wn * 32 * 136 + boffK);
#pragma unroll
        for (int ks = 0; ks < 8; ks++) {
            uint32_t qa1[4], qa2[4];
            ldsm4(qa1, qb1 + 2 * (ks * 16));
            ldsm4(qa2, qb2 + 2 * (ks * 16));
#pragma unroll
            for (int ng = 0; ng < 2; ng++) {
                uint32_t kb1[4], kb2[4];
                ldsm4(kb1, kb1b + 2 * (ng * 16 * 136 + ks * 16));
                ldsm4(kb2, kb2b + 2 * (ng * 16 * 136 + ks * 16));
                mma16(sf[2*ng],     qa1, kb1);
                mma16(sf[2*ng + 1], qa1, kb1 + 2);
                mma16(sf[2*ng],     qa1, kb2);
                mma16(sf[2*ng + 1], qa1, kb2 + 2);
                mma16(sf[2*ng],     qa2, kb1);
                mma16(sf[2*ng + 1], qa2, kb1 + 2);
            }
        }

        // causal mask: only the diagonal tile (kt == qt)
        if (kt == qt) {
#pragma unroll
            for (int ni = 0; ni < 4; ni++) {
                int col = wn * 32 + ni * 8 + tg * 2;   // local col in [0,64)
                if (col     > r0)     sf[ni][0] = -INFINITY;
                if (col + 1 > r0)     sf[ni][1] = -INFINITY;
                if (col     > r0 + 8) sf[ni][2] = -INFINITY;
                if (col + 1 > r0 + 8) sf[ni][3] = -INFINITY;
            }
        }

        // row max across this warp's 32 cols, then across the 2 n-warps (pair)
        float pm0 = -INFINITY, pm1 = -INFINITY;
#pragma unroll
        for (int ni = 0; ni < 4; ni++) {
            pm0 = fmaxf(pm0, fmaxf(sf[ni][0], sf[ni][1]));
            pm1 = fmaxf(pm1, fmaxf(sf[ni][2], sf[ni][3]));
        }
        pm0 = fmaxf(pm0, __shfl_xor_sync(0xffffffffu, pm0, 1));
        pm0 = fmaxf(pm0, __shfl_xor_sync(0xffffffffu, pm0, 2));
        pm1 = fmaxf(pm1, __shfl_xor_sync(0xffffffffu, pm1, 1));
        pm1 = fmaxf(pm1, __shfl_xor_sync(0xffffffffu, pm1, 2));
        if (tg == 0) { smax[wn * 64 + r0] = pm0; smax[wn * 64 + r1] = pm1; }
        asm volatile("bar.sync %0, 64;" :: "r"(1 + wm) : "memory");

        float m0n = fmaxf(mrun0, fmaxf(smax[r0], smax[64 + r0]));
        float m1n = fmaxf(mrun1, fmaxf(smax[r1], smax[64 + r1]));
        float f0 = __expf(mrun0 - m0n);
        float f1 = __expf(mrun1 - m1n);
        mrun0 = m0n; mrun1 = m1n;

        // exp, partial sums, write P (fp16)
        float ps0 = 0.f, ps1 = 0.f;
#pragma unroll
        for (int ni = 0; ni < 4; ni++) {
            float e0 = __expf(sf[ni][0] - m0n);
            float e1 = __expf(sf[ni][1] - m0n);
            float e2 = __expf(sf[ni][2] - m1n);
            float e3 = __expf(sf[ni][3] - m1n);
            ps0 += e0 + e1; ps1 += e2 + e3;
            int col = wn * 32 + ni * 8 + tg * 2;
            __half2 p01 = __floats2half2_rn(e0, e1);
            __half2 p23 = __floats2half2_rn(e2, e3);
            *(uint32_t*)&shh[PH_ + r0 * 72 + col] = *(uint32_t*)&p01;
            *(uint32_t*)&shh[PH_ + r1 * 72 + col] = *(uint32_t*)&p23;
        }
        ps0 += __shfl_xor_sync(0xffffffffu, ps0, 1);
        ps0 += __shfl_xor_sync(0xffffffffu, ps0, 2);
        ps1 += __shfl_xor_sync(0xffffffffu, ps1, 1);
        ps1 += __shfl_xor_sync(0xffffffffu, ps1, 2);
        if (tg == 0) { ssum[wn * 64 + r0] = ps0; ssum[wn * 64 + r1] = ps1; }

        // rescale O while the pair barrier drains
#pragma unroll
        for (int ni = 0; ni < 8; ni++) {
            of[ni][0] *= f0; of[ni][1] *= f0;
            of[ni][2] *= f1; of[ni][3] *= f1;
        }
        asm volatile("bar.sync %0, 64;" :: "r"(1 + wm) : "memory");
        lrun0 = lrun0 * f0 + ssum[r0] + ssum[64 + r0];
        lrun1 = lrun1 * f1 + ssum[r1] + ssum[64 + r1];

        // O += P V  (fp16 single), ldmatrix frags
        const uint32_t pb = sb + 2 * (PH_ + wm * 16 * 72 + aoffP);
        const uint32_t vbb = sb + 2 * (VS_ + wn * 64 + voffV);
#pragma unroll
        for (int ks = 0; ks < 4; ks++) {
            uint32_t pa[4];
            ldsm4(pa, pb + 2 * (ks * 16));
#pragma unroll
            for (int ng = 0; ng < 4; ng++) {
                uint32_t vb[4];
                ldsm4t(vb, vbb + 2 * (ks * 16 * 136 + ng * 16));
                mma16(of[2*ng],     pa, vb);
                mma16(of[2*ng + 1], pa, vb + 2);
            }
        }
    }

    // epilogue
    float inv0 = 1.f / lrun0;
    float inv1 = 1.f / lrun1;
    int grow = qt * 64 + r0;
#pragma unroll
    for (int ni = 0; ni < 8; ni++) {
        int col = wn * 64 + ni * 8 + tg * 2;
        *(float2*)&out[base + (size_t)grow * H_ + col] =
            make_float2(of[ni][0] * inv0, of[ni][1] * inv0);
        *(float2*)&out[base + (size_t)(grow + 8) * H_ + col] =
            make_float2(of[ni][2] * inv1, of[ni][3] * inv1);
    }
}

// ---------------------------------------------------------------------------
extern "C" void kernel_launch(void* const* d_in, const int* in_sizes, int n_in,
                              void* d_out, int out_size)
{
    const float* x  = (const float*)d_in[0];
    const float* Wq = (const float*)d_in[1];
    const float* Wk = (const float*)d_in[2];
    const float* Wv = (const float*)d_in[3];
    float* out = (float*)d_out;

    prep_w<<<dim3(E_/32, H_/32, 3), 256>>>(Wq, Wk, Wv);

    cudaFuncSetAttribute(proj_tc,
                         cudaFuncAttributeMaxDynamicSharedMemorySize, PJ_SMEM);
    proj_tc<<<dim3(BT_/64, 3), 256, PJ_SMEM>>>(x);

    cudaFuncSetAttribute(attn_tc,
                         cudaFuncAttributeMaxDynamicSharedMemorySize, A_SMEM);
    attn_tc<<<dim3(T_/64, B_), 256, A_SMEM>>>(out);
}